// round 6
// baseline (speedup 1.0000x reference)
#include <cuda_runtime.h>
#include <cuda_bf16.h>
#include <math_constants.h>

typedef unsigned long long ull;

// ---------------- f32x2 helpers ----------------
__device__ __forceinline__ ull pk2(float lo, float hi) {
    ull r; asm("mov.b64 %0, {%1, %2};" : "=l"(r) : "f"(lo), "f"(hi)); return r;
}
__device__ __forceinline__ ull dup2(float v) {
    ull r; asm("mov.b64 %0, {%1, %1};" : "=l"(r) : "f"(v)); return r;
}
__device__ __forceinline__ void unpk2(ull v, float& lo, float& hi) {
    asm("mov.b64 {%0, %1}, %2;" : "=f"(lo), "=f"(hi) : "l"(v));
}
__device__ __forceinline__ void fma2(ull& acc, ull a, ull b) {
    asm("fma.rn.f32x2 %0, %1, %2, %0;" : "+l"(acc) : "l"(a), "l"(b));
}
__device__ __forceinline__ void add2(ull& a, ull b) {
    asm("add.rn.f32x2 %0, %0, %1;" : "+l"(a) : "l"(b));
}
__device__ __forceinline__ void lds2(ull& a, ull& b, unsigned addr) {
    asm("ld.shared.v2.u64 {%0, %1}, [%2];" : "=l"(a), "=l"(b) : "r"(addr));
}
__device__ __forceinline__ void lds128f(float& x, float& y, float& z, float& w, unsigned a) {
    asm("ld.shared.v4.f32 {%0, %1, %2, %3}, [%4];"
        : "=f"(x), "=f"(y), "=f"(z), "=f"(w) : "r"(a));
}
__device__ __forceinline__ float lds32(unsigned a) {
    float v; asm("ld.shared.f32 %0, [%1];" : "=f"(v) : "r"(a)); return v;
}
__device__ __forceinline__ ull lds64(unsigned a) {
    ull v; asm("ld.shared.b64 %0, [%1];" : "=l"(v) : "r"(a)); return v;
}
__device__ __forceinline__ void sts64(unsigned addr, ull v) {
    asm volatile("st.shared.b64 [%0], %1;" :: "r"(addr), "l"(v));
}
__device__ __forceinline__ void cpasync16(unsigned saddr, const void* g) {
    asm volatile("cp.async.ca.shared.global [%0], [%1], 16;" :: "r"(saddr), "l"(g));
}
#define CP_COMMIT()   asm volatile("cp.async.commit_group;")
#define CP_WAIT_ALL() asm volatile("cp.async.wait_group 0;")
__device__ __forceinline__ unsigned s2u(const void* p) {
    return (unsigned)__cvta_generic_to_shared(p);
}

// ---------------- scratch ----------------
__device__ __align__(16) float g_A1[2048 * 32 * 288];  // conv1 out [b][c][12 rows, stride 24]
__device__ __align__(16) float g_A2[1024 * 2048];      // conv2 out TRANSPOSED [feature k][image m]
__device__ __align__(16) float g_F1[2048 * 512];       // fc1 partial (K 0..511)
__device__ __align__(16) float g_F1b[2048 * 512];      // fc1 partial (K 512..1023)
__device__ __align__(16) float g_W2T[800 * 64];        // conv2 weights [k][co]
__device__ __align__(16) float g_W1T[1024 * 512];      // fc1 weights [k][n]

#define BN_INV 0.9999950000374997f

template <int NW>
__device__ __forceinline__ float blockReduce(float v) {
    __shared__ float r[NW];
    #pragma unroll
    for (int o = 16; o > 0; o >>= 1) v += __shfl_xor_sync(0xFFFFFFFFu, v, o);
    int wid = threadIdx.x >> 5, lane = threadIdx.x & 31;
    __syncthreads();
    if (lane == 0) r[wid] = v;
    __syncthreads();
    float t = 0.f;
    #pragma unroll
    for (int i = 0; i < NW; i++) t += r[i];
    return t;
}

__device__ __forceinline__ float tern_val(float v, float delta, float alpha) {
    return (v > delta) ? alpha : ((v < -delta) ? -alpha : 0.f);
}

// ---------------- k_pre: both weight transposes ----------------
#define N_W2 (64 * 800)
#define N_W1 (512 * 1024)
__global__ void k_pre(const float* __restrict__ w2, const float* __restrict__ w1) {
    int i = blockIdx.x * 256 + threadIdx.x;
    if (i < N_W2) {
        int co = i / 800, k = i % 800;
        g_W2T[k * 64 + co] = w2[i];
    } else if (i < N_W2 + N_W1) {
        int j = i - N_W2;
        int n = j / 1024, k = j % 1024;
        g_W1T[k * 512 + n] = w1[j];
    }
}

// ================= conv1 (unchanged) =================
#define SC1STR 578
__global__ void __launch_bounds__(256, 2) k_conv1(
    const float* __restrict__ x, const float* __restrict__ w,
    const float* __restrict__ bias, const float* __restrict__ bng,
    const float* __restrict__ bnb)
{
    extern __shared__ float sm[];
    float* sx  = sm;            // 784
    float* sw  = sm + 784;      // 800
    float* sc1 = sm + 1584;     // 32*578
    __shared__ float sb[32], sscale[32], sbeta[32];

    int b = blockIdx.x, tid = threadIdx.x;
    const float* xb = x + b * 784;
    for (int i = tid; i < 784; i += 256) sx[i] = xb[i];
    for (int i = tid; i < 800; i += 256) sw[i] = w[i];
    if (tid < 32) {
        sb[tid]     = bias[tid];
        sscale[tid] = bng[tid] * BN_INV;
        sbeta[tid]  = bnb[tid];
    }
    __syncthreads();

    int c = tid & 31, rg = tid >> 5;
    float wr[25];
    #pragma unroll
    for (int i = 0; i < 25; i++) wr[i] = sw[c * 25 + i];
    float bv = sb[c];

    unsigned scb = s2u(sm) + (1584 + c * SC1STR) * 4;
    float asum = 0.f;

    #pragma unroll
    for (int rr = 0; rr < 3; rr++) {
        int r = rg * 3 + rr;
        ull acc[12];
        #pragma unroll
        for (int j = 0; j < 12; j++) acc[j] = dup2(bv);

        #pragma unroll
        for (int ky = 0; ky < 5; ky++) {
            const float4* xr4 = (const float4*)(sx + (r + ky) * 28);
            float v[28];
            #pragma unroll
            for (int q = 0; q < 7; q++) {
                float4 t = xr4[q];
                v[q*4] = t.x; v[q*4+1] = t.y; v[q*4+2] = t.z; v[q*4+3] = t.w;
            }
            #pragma unroll
            for (int kx = 0; kx < 5; kx++) {
                ull wd = dup2(wr[ky * 5 + kx]);
                #pragma unroll
                for (int j = 0; j < 12; j++)
                    fma2(acc[j], pk2(v[kx + 2*j], v[kx + 2*j + 1]), wd);
            }
        }
        unsigned ro = scb + r * 24 * 4;
        #pragma unroll
        for (int j = 0; j < 12; j++) {
            sts64(ro + j * 8, acc[j]);
            float lo, hi; unpk2(acc[j], lo, hi);
            asum += fabsf(lo) + fabsf(hi);
        }
    }

    float tot = blockReduce<8>(asum);
    float delta = 0.7f * tot / 18432.0f;

    float ms = 0.f, mc = 0.f;
    #pragma unroll
    for (int rr = 0; rr < 3; rr++) {
        int r = rg * 3 + rr;
        #pragma unroll
        for (int t = 0; t < 24; t++) {
            float a = fabsf(sc1[c * SC1STR + r * 24 + t]);
            if (a > delta) { ms += a; mc += 1.f; }
        }
    }
    ms = blockReduce<8>(ms);
    mc = blockReduce<8>(mc);
    float alpha = ms / mc;

    for (int u = tid; u < 4608; u += 256) {
        int cc = u / 144, p = u % 144;
        int py = p / 12, px = p % 12;
        const float* q = sc1 + cc * SC1STR + (2 * py) * 24 + 2 * px;
        float sc = sscale[cc], bt = sbeta[cc];
        float m = -CUDART_INF_F, v;
        v = q[0];  m = fmaxf(m, fmaf(tern_val(v, delta, alpha), sc, bt));
        v = q[1];  m = fmaxf(m, fmaf(tern_val(v, delta, alpha), sc, bt));
        v = q[24]; m = fmaxf(m, fmaf(tern_val(v, delta, alpha), sc, bt));
        v = q[25]; m = fmaxf(m, fmaf(tern_val(v, delta, alpha), sc, bt));
        g_A1[b * 9216 + cc * 288 + py * 24 + px] = fmaxf(m, 0.f);
    }
}

// ================= conv2: 2 img/block, 512 thr, K-split across warp halves =================
// warps 0-7: ci 0-15, warps 8-15: ci 16-31; each warp = 8 out-channels, lane = pos(lane,lane+32)
// smem: sin[18432] | sov[8192]{ wbuf 2bufs x 2halves x 1600 ; later partials/sout }
__global__ void __launch_bounds__(512, 2) k_conv2(
    const float* __restrict__ bias, const float* __restrict__ bng,
    const float* __restrict__ bnb)
{
    extern __shared__ float sm[];
    float* sin_ = sm;                 // 18432 floats
    float* sov  = sm + 18432;         // 8192 floats (32KB)
    __shared__ float sb2[64], sscale[64], sbeta[64];

    int b = blockIdx.x, tid = threadIdx.x;
    unsigned sin_u = s2u(sin_);
    unsigned sov_u = s2u(sov);

    // stage 2 images of input
    const float* gin = g_A1 + b * 18432;
    #pragma unroll
    for (int i = 0; i < 9; i++) {
        int o = tid + i * 512;                 // 0..4607 float4 chunks
        cpasync16(sin_u + o * 16, gin + o * 4);
    }
    // stage weights for step 0, both halves (ci=0 and ci=16)
    for (int o = tid; o < 800; o += 512) {
        int h = (o >= 400), idx = o - h * 400;
        cpasync16(sov_u + h * 6400 + idx * 16, g_W2T + (h * 16) * 1600 + idx * 4);
    }
    CP_COMMIT();

    if (tid < 64) {
        sb2[tid]    = bias[tid];
        sscale[tid] = bng[tid] * BN_INV;
        sbeta[tid]  = bnb[tid];
    }
    CP_WAIT_ALL();
    __syncthreads();

    int w = tid >> 5, lane = tid & 31;
    int wh = w >> 3, wg = w & 7;              // k-half, co-group
    int py = lane >> 3, px = lane & 7;

    ull acc[2][2][4];
    #pragma unroll
    for (int j = 0; j < 4; j++) {
        ull bvj = wh ? 0ull : pk2(sb2[wg * 8 + 2 * j], sb2[wg * 8 + 2 * j + 1]);
        acc[0][0][j] = bvj; acc[0][1][j] = bvj;
        acc[1][0][j] = bvj; acc[1][1][j] = bvj;
    }

    unsigned abase = sin_u + (py * 24 + px) * 4;
    unsigned wlane = wg * 32;

    for (int s = 0; s < 16; s++) {
        int cur = s & 1;
        if (s < 15) {
            for (int o = tid; o < 800; o += 512) {
                int h = (o >= 400), idx = o - h * 400;
                int ci = h * 16 + s + 1;
                cpasync16(sov_u + (cur ^ 1) * 12800 + h * 6400 + idx * 16,
                          g_W2T + ci * 1600 + idx * 4);
            }
            CP_COMMIT();
        }
        int ci = wh * 16 + s;
        unsigned swc = sov_u + cur * 12800 + wh * 6400 + wlane;
        unsigned a0 = abase + ci * 1152;
        #pragma unroll
        for (int t = 0; t < 25; t++) {
            const int io = ((t / 5) * 24 + (t % 5)) * 4;
            ull w01, w23, w45, w67;
            lds2(w01, w23, swc + t * 256);
            lds2(w45, w67, swc + t * 256 + 16);
            #pragma unroll
            for (int img = 0; img < 2; img++) {
                unsigned ai = a0 + img * 36864 + io;
                ull d0 = dup2(lds32(ai));
                ull d1 = dup2(lds32(ai + 384));
                fma2(acc[img][0][0], d0, w01); fma2(acc[img][0][1], d0, w23);
                fma2(acc[img][0][2], d0, w45); fma2(acc[img][0][3], d0, w67);
                fma2(acc[img][1][0], d1, w01); fma2(acc[img][1][1], d1, w23);
                fma2(acc[img][1][2], d1, w45); fma2(acc[img][1][3], d1, w67);
            }
        }
        if (s < 15) { CP_WAIT_ALL(); __syncthreads(); }
    }

    // combine K-halves: warps 8-15 dump partials, warps 0-7 add
    __syncthreads();
    if (wh == 1) {
        #pragma unroll
        for (int img = 0; img < 2; img++)
            #pragma unroll
            for (int pz = 0; pz < 2; pz++)
                #pragma unroll
                for (int j = 0; j < 4; j++) {
                    int idx = ((img * 2 + pz) * 4 + j) * 256 + wg * 32 + lane;
                    sts64(sov_u + idx * 8, acc[img][pz][j]);
                }
    }
    __syncthreads();
    if (wh == 0) {
        #pragma unroll
        for (int img = 0; img < 2; img++)
            #pragma unroll
            for (int pz = 0; pz < 2; pz++)
                #pragma unroll
                for (int j = 0; j < 4; j++) {
                    int idx = ((img * 2 + pz) * 4 + j) * 256 + wg * 32 + lane;
                    add2(acc[img][pz][j], lds64(sov_u + idx * 8));
                }
    }

    // per-image stats (warps 0-7 hold final accs; others contribute 0)
    float dlt[2], alf[2];
    #pragma unroll
    for (int img = 0; img < 2; img++) {
        float as = 0.f;
        if (wh == 0) {
            #pragma unroll
            for (int pz = 0; pz < 2; pz++)
                #pragma unroll
                for (int j = 0; j < 4; j++) {
                    float lo, hi; unpk2(acc[img][pz][j], lo, hi);
                    as += fabsf(lo) + fabsf(hi);
                }
        }
        dlt[img] = 0.7f * blockReduce<16>(as) / 4096.0f;
    }
    #pragma unroll
    for (int img = 0; img < 2; img++) {
        float ms = 0.f, mc = 0.f;
        if (wh == 0) {
            #pragma unroll
            for (int pz = 0; pz < 2; pz++)
                #pragma unroll
                for (int j = 0; j < 4; j++) {
                    float lo, hi; unpk2(acc[img][pz][j], lo, hi);
                    float a = fabsf(lo); if (a > dlt[img]) { ms += a; mc += 1.f; }
                    a = fabsf(hi);       if (a > dlt[img]) { ms += a; mc += 1.f; }
                }
        }
        ms = blockReduce<16>(ms);
        mc = blockReduce<16>(mc);
        alf[img] = ms / mc;
    }

    // stage conv outputs (reuse sov; partial reads finished before the reductions' barriers)
    float* sout = sov;
    if (wh == 0) {
        #pragma unroll
        for (int img = 0; img < 2; img++)
            #pragma unroll
            for (int pz = 0; pz < 2; pz++) {
                int p = lane + pz * 32;
                #pragma unroll
                for (int j = 0; j < 4; j++) {
                    float lo, hi; unpk2(acc[img][pz][j], lo, hi);
                    sout[img * 4096 + (wg * 8 + 2 * j) * 64 + p]     = lo;
                    sout[img * 4096 + (wg * 8 + 2 * j + 1) * 64 + p] = hi;
                }
            }
    }
    __syncthreads();

    // tern + BN + pool + relu -> g_A2 transposed [feature][image]
    for (int u = tid; u < 2048; u += 512) {
        int img = u >> 10, idx = u & 1023;
        int c = idx >> 4, p = idx & 15;
        int py2 = p >> 2, px2 = p & 3;
        const float* q = sout + img * 4096 + c * 64 + (2 * py2) * 8 + 2 * px2;
        float delta = dlt[img], alpha = alf[img];
        float sc = sscale[c], bt = sbeta[c];
        float m = -CUDART_INF_F, v;
        v = q[0]; m = fmaxf(m, fmaf(tern_val(v, delta, alpha), sc, bt));
        v = q[1]; m = fmaxf(m, fmaf(tern_val(v, delta, alpha), sc, bt));
        v = q[8]; m = fmaxf(m, fmaf(tern_val(v, delta, alpha), sc, bt));
        v = q[9]; m = fmaxf(m, fmaf(tern_val(v, delta, alpha), sc, bt));
        g_A2[idx * 2048 + b * 2 + img] = fmaxf(m, 0.f);
    }
}

// ================= fc1: 64x64 tile, K-split by 2, grid 512 =================
__global__ void __launch_bounds__(256) k_fc1()
{
    extern __shared__ float sm[];
    float* As = sm;              // [2][32][64]
    float* Bs = sm + 4096;       // [2][32][64]

    int bn = blockIdx.x * 64, bm = blockIdx.y * 64;
    int kbase = blockIdx.z * 512;
    int tid = threadIdx.x, tx = tid & 15, ty = tid >> 4;
    unsigned as_u = s2u(As), bs_u = s2u(Bs);

    ull acc[4][2];
    #pragma unroll
    for (int c = 0; c < 4; c++) { acc[c][0] = 0ull; acc[c][1] = 0ull; }

    // stage chunk 0
    #pragma unroll
    for (int i = 0; i < 2; i++) {
        int o = tid + i * 256;                 // 0..511
        int kk = o >> 4, seg = o & 15;
        cpasync16(as_u + (kk * 64 + seg * 4) * 4, g_A2 + (kbase + kk) * 2048 + bm + seg * 4);
        cpasync16(bs_u + (kk * 64 + seg * 4) * 4, g_W1T + (kbase + kk) * 512 + bn + seg * 4);
    }
    CP_COMMIT();
    CP_WAIT_ALL();
    __syncthreads();

    for (int kc = 0; kc < 16; kc++) {
        int cur = kc & 1;
        if (kc < 15) {
            int k0 = kbase + (kc + 1) * 32, nb = cur ^ 1;
            #pragma unroll
            for (int i = 0; i < 2; i++) {
                int o = tid + i * 256;
                int kk = o >> 4, seg = o & 15;
                cpasync16(as_u + (nb * 2048 + kk * 64 + seg * 4) * 4,
                          g_A2 + (k0 + kk) * 2048 + bm + seg * 4);
                cpasync16(bs_u + (nb * 2048 + kk * 64 + seg * 4) * 4,
                          g_W1T + (k0 + kk) * 512 + bn + seg * 4);
            }
            CP_COMMIT();
        }
        unsigned ab = as_u + cur * 8192 + ty * 16;
        unsigned bb = bs_u + cur * 8192 + tx * 16;
        #pragma unroll
        for (int kk = 0; kk < 32; kk++) {
            ull a01, a23;
            lds2(a01, a23, ab + kk * 256);
            float b0, b1, b2, b3;
            lds128f(b0, b1, b2, b3, bb + kk * 256);
            ull d;
            d = dup2(b0); fma2(acc[0][0], a01, d); fma2(acc[0][1], a23, d);
            d = dup2(b1); fma2(acc[1][0], a01, d); fma2(acc[1][1], a23, d);
            d = dup2(b2); fma2(acc[2][0], a01, d); fma2(acc[2][1], a23, d);
            d = dup2(b3); fma2(acc[3][0], a01, d); fma2(acc[3][1], a23, d);
        }
        if (kc < 15) { CP_WAIT_ALL(); __syncthreads(); }
    }

    float* dst = blockIdx.z ? g_F1b : g_F1;
    #pragma unroll
    for (int c = 0; c < 4; c++) {
        int r0 = bm + ty * 4;
        float lo, hi;
        unpk2(acc[c][0], lo, hi);
        dst[r0 * 512 + bn + tx * 4 + c]       = lo;
        dst[(r0 + 1) * 512 + bn + tx * 4 + c] = hi;
        unpk2(acc[c][1], lo, hi);
        dst[(r0 + 2) * 512 + bn + tx * 4 + c] = lo;
        dst[(r0 + 3) * 512 + bn + tx * 4 + c] = hi;
    }
}

// ================= head: sum partials + bias, tern+relu -> fc2 -> tern =================
__global__ void __launch_bounds__(128) k_head(
    const float* __restrict__ b1, const float* __restrict__ W2,
    const float* __restrict__ b2, float* __restrict__ out)
{
    __shared__ float sh[512];
    __shared__ float so[10];

    int b = blockIdx.x, tid = threadIdx.x;
    float4 va = ((const float4*)(g_F1  + b * 512))[tid];
    float4 vb = ((const float4*)(g_F1b + b * 512))[tid];
    float4 bi = ((const float4*)b1)[tid];
    float vv[4];
    vv[0] = va.x + vb.x + bi.x;
    vv[1] = va.y + vb.y + bi.y;
    vv[2] = va.z + vb.z + bi.z;
    vv[3] = va.w + vb.w + bi.w;

    float asum = fabsf(vv[0]) + fabsf(vv[1]) + fabsf(vv[2]) + fabsf(vv[3]);
    float tot = blockReduce<4>(asum);
    float delta = 0.7f * tot / 512.0f;

    float ms = 0.f, mc = 0.f;
    #pragma unroll
    for (int i = 0; i < 4; i++) {
        float a = fabsf(vv[i]);
        if (a > delta) { ms += a; mc += 1.f; }
    }
    ms = blockReduce<4>(ms);
    mc = blockReduce<4>(mc);
    float alpha = ms / mc;

    #pragma unroll
    for (int i = 0; i < 4; i++)
        sh[tid * 4 + i] = (vv[i] > delta) ? alpha : 0.f;
    __syncthreads();

    int wd = tid >> 5, ln = tid & 31;
    for (int r = wd; r < 10; r += 4) {
        float s = 0.f;
        const float* wr = W2 + r * 512;
        for (int j = ln; j < 512; j += 32) s += sh[j] * wr[j];
        #pragma unroll
        for (int o = 16; o > 0; o >>= 1) s += __shfl_xor_sync(0xFFFFFFFFu, s, o);
        if (ln == 0) so[r] = s + b2[r];
    }
    __syncthreads();

    if (tid == 0) {
        float s = 0.f;
        #pragma unroll
        for (int n = 0; n < 10; n++) s += fabsf(so[n]);
        float d2 = 0.7f * s / 10.0f;
        float ms2 = 0.f, c2 = 0.f;
        #pragma unroll
        for (int n = 0; n < 10; n++) {
            float a = fabsf(so[n]);
            if (a > d2) { ms2 += a; c2 += 1.f; }
        }
        float a2 = ms2 / c2;
        #pragma unroll
        for (int n = 0; n < 10; n++)
            out[b * 10 + n] = tern_val(so[n], d2, a2);
    }
}

// ---------------- launch ----------------
extern "C" void kernel_launch(void* const* d_in, const int* in_sizes, int n_in,
                              void* d_out, int out_size)
{
    (void)in_sizes; (void)n_in; (void)out_size;
    const float* x       = (const float*)d_in[0];
    const float* conv1_w = (const float*)d_in[1];
    const float* conv1_b = (const float*)d_in[2];
    const float* bn1_g   = (const float*)d_in[3];
    const float* bn1_b   = (const float*)d_in[4];
    const float* conv2_w = (const float*)d_in[5];
    const float* conv2_b = (const float*)d_in[6];
    const float* bn2_g   = (const float*)d_in[7];
    const float* bn2_b   = (const float*)d_in[8];
    const float* fc1_w   = (const float*)d_in[9];
    const float* fc1_b   = (const float*)d_in[10];
    const float* fc2_w   = (const float*)d_in[11];
    const float* fc2_b   = (const float*)d_in[12];
    float* out = (float*)d_out;

    const int SMEM1 = (1584 + 32 * SC1STR) * 4;          // ~80.3 KB
    const int SMEM2 = (18432 + 8192) * 4;                // 106.5 KB
    const int SMEMF = (4096 + 4096) * 4;                 // 32 KB
    cudaFuncSetAttribute(k_conv1, cudaFuncAttributeMaxDynamicSharedMemorySize, SMEM1);
    cudaFuncSetAttribute(k_conv2, cudaFuncAttributeMaxDynamicSharedMemorySize, SMEM2);
    cudaFuncSetAttribute(k_fc1,   cudaFuncAttributeMaxDynamicSharedMemorySize, SMEMF);

    k_pre<<<(N_W2 + N_W1 + 255) / 256, 256>>>(conv2_w, fc1_w);
    k_conv1<<<2048, 256, SMEM1>>>(x, conv1_w, conv1_b, bn1_g, bn1_b);
    k_conv2<<<1024, 512, SMEM2>>>(conv2_b, bn2_g, bn2_b);
    k_fc1<<<dim3(8, 32, 2), 256, SMEMF>>>();
    k_head<<<2048, 128>>>(fc1_b, fc2_w, fc2_b, out);
}

// round 7
// speedup vs baseline: 1.4933x; 1.4933x over previous
#include <cuda_runtime.h>
#include <cuda_bf16.h>
#include <math_constants.h>

typedef unsigned long long ull;

// ---------------- f32x2 helpers ----------------
__device__ __forceinline__ ull pk2(float lo, float hi) {
    ull r; asm("mov.b64 %0, {%1, %2};" : "=l"(r) : "f"(lo), "f"(hi)); return r;
}
__device__ __forceinline__ ull dup2(float v) {
    ull r; asm("mov.b64 %0, {%1, %1};" : "=l"(r) : "f"(v)); return r;
}
__device__ __forceinline__ void unpk2(ull v, float& lo, float& hi) {
    asm("mov.b64 {%0, %1}, %2;" : "=f"(lo), "=f"(hi) : "l"(v));
}
__device__ __forceinline__ void fma2(ull& acc, ull a, ull b) {
    asm("fma.rn.f32x2 %0, %1, %2, %0;" : "+l"(acc) : "l"(a), "l"(b));
}
__device__ __forceinline__ void lds2(ull& a, ull& b, unsigned addr) {
    asm("ld.shared.v2.u64 {%0, %1}, [%2];" : "=l"(a), "=l"(b) : "r"(addr));
}
__device__ __forceinline__ void lds128f(float& x, float& y, float& z, float& w, unsigned a) {
    asm("ld.shared.v4.f32 {%0, %1, %2, %3}, [%4];"
        : "=f"(x), "=f"(y), "=f"(z), "=f"(w) : "r"(a));
}
__device__ __forceinline__ float lds32(unsigned a) {
    float v; asm("ld.shared.f32 %0, [%1];" : "=f"(v) : "r"(a)); return v;
}
__device__ __forceinline__ void sts64(unsigned addr, ull v) {
    asm volatile("st.shared.b64 [%0], %1;" :: "r"(addr), "l"(v));
}
__device__ __forceinline__ void cpasync16(unsigned saddr, const void* g) {
    asm volatile("cp.async.ca.shared.global [%0], [%1], 16;" :: "r"(saddr), "l"(g));
}
#define CP_COMMIT()   asm volatile("cp.async.commit_group;")
#define CP_WAIT_ALL() asm volatile("cp.async.wait_group 0;")
__device__ __forceinline__ unsigned s2u(const void* p) {
    return (unsigned)__cvta_generic_to_shared(p);
}

// ---------------- scratch ----------------
__device__ __align__(16) float g_A1[2048 * 32 * 288];  // conv1 out [b][c][12 rows, stride 24]
__device__ __align__(16) float g_A2[1024 * 2048];      // conv2 out TRANSPOSED [feature k][image m]
__device__ __align__(16) float g_F1[2048 * 512];       // fc1 pre-ternarize [m][n]
__device__ __align__(16) float g_W2T[800 * 64];        // conv2 weights [k][co]
__device__ __align__(16) float g_W1T[1024 * 512];      // fc1 weights [k][n]

#define BN_INV 0.9999950000374997f

template <int NW>
__device__ __forceinline__ float blockReduce(float v) {
    __shared__ float r[NW];
    #pragma unroll
    for (int o = 16; o > 0; o >>= 1) v += __shfl_xor_sync(0xFFFFFFFFu, v, o);
    int wid = threadIdx.x >> 5, lane = threadIdx.x & 31;
    __syncthreads();
    if (lane == 0) r[wid] = v;
    __syncthreads();
    float t = 0.f;
    #pragma unroll
    for (int i = 0; i < NW; i++) t += r[i];
    return t;
}

__device__ __forceinline__ float tern_val(float v, float delta, float alpha) {
    return (v > delta) ? alpha : ((v < -delta) ? -alpha : 0.f);
}

// ---------------- k_pre: both weight transposes ----------------
#define N_W2 (64 * 800)
#define N_W1 (512 * 1024)
__global__ void k_pre(const float* __restrict__ w2, const float* __restrict__ w1) {
    int i = blockIdx.x * 256 + threadIdx.x;
    if (i < N_W2) {
        int co = i / 800, k = i % 800;
        g_W2T[k * 64 + co] = w2[i];
    } else if (i < N_W2 + N_W1) {
        int j = i - N_W2;
        int n = j / 1024, k = j % 1024;
        g_W1T[k * 512 + n] = w1[j];
    }
}

// ================= conv1 (R5, unchanged) =================
#define SC1STR 578
__global__ void __launch_bounds__(256, 2) k_conv1(
    const float* __restrict__ x, const float* __restrict__ w,
    const float* __restrict__ bias, const float* __restrict__ bng,
    const float* __restrict__ bnb)
{
    extern __shared__ float sm[];
    float* sx  = sm;            // 784
    float* sw  = sm + 784;      // 800
    float* sc1 = sm + 1584;     // 32*578
    __shared__ float sb[32], sscale[32], sbeta[32];

    int b = blockIdx.x, tid = threadIdx.x;
    const float* xb = x + b * 784;
    for (int i = tid; i < 784; i += 256) sx[i] = xb[i];
    for (int i = tid; i < 800; i += 256) sw[i] = w[i];
    if (tid < 32) {
        sb[tid]     = bias[tid];
        sscale[tid] = bng[tid] * BN_INV;
        sbeta[tid]  = bnb[tid];
    }
    __syncthreads();

    int c = tid & 31, rg = tid >> 5;
    float wr[25];
    #pragma unroll
    for (int i = 0; i < 25; i++) wr[i] = sw[c * 25 + i];
    float bv = sb[c];

    unsigned scb = s2u(sm) + (1584 + c * SC1STR) * 4;
    float asum = 0.f;

    #pragma unroll
    for (int rr = 0; rr < 3; rr++) {
        int r = rg * 3 + rr;
        ull acc[12];
        #pragma unroll
        for (int j = 0; j < 12; j++) acc[j] = dup2(bv);

        #pragma unroll
        for (int ky = 0; ky < 5; ky++) {
            const float4* xr4 = (const float4*)(sx + (r + ky) * 28);
            float v[28];
            #pragma unroll
            for (int q = 0; q < 7; q++) {
                float4 t = xr4[q];
                v[q*4] = t.x; v[q*4+1] = t.y; v[q*4+2] = t.z; v[q*4+3] = t.w;
            }
            #pragma unroll
            for (int kx = 0; kx < 5; kx++) {
                ull wd = dup2(wr[ky * 5 + kx]);
                #pragma unroll
                for (int j = 0; j < 12; j++)
                    fma2(acc[j], pk2(v[kx + 2*j], v[kx + 2*j + 1]), wd);
            }
        }
        unsigned ro = scb + r * 24 * 4;
        #pragma unroll
        for (int j = 0; j < 12; j++) {
            sts64(ro + j * 8, acc[j]);
            float lo, hi; unpk2(acc[j], lo, hi);
            asum += fabsf(lo) + fabsf(hi);
        }
    }

    float tot = blockReduce<8>(asum);
    float delta = 0.7f * tot / 18432.0f;

    float ms = 0.f, mc = 0.f;
    #pragma unroll
    for (int rr = 0; rr < 3; rr++) {
        int r = rg * 3 + rr;
        #pragma unroll
        for (int t = 0; t < 24; t++) {
            float a = fabsf(sc1[c * SC1STR + r * 24 + t]);
            if (a > delta) { ms += a; mc += 1.f; }
        }
    }
    ms = blockReduce<8>(ms);
    mc = blockReduce<8>(mc);
    float alpha = ms / mc;

    for (int u = tid; u < 4608; u += 256) {
        int cc = u / 144, p = u % 144;
        int py = p / 12, px = p % 12;
        const float* q = sc1 + cc * SC1STR + (2 * py) * 24 + 2 * px;
        float sc = sscale[cc], bt = sbeta[cc];
        float m = -CUDART_INF_F, v;
        v = q[0];  m = fmaxf(m, fmaf(tern_val(v, delta, alpha), sc, bt));
        v = q[1];  m = fmaxf(m, fmaf(tern_val(v, delta, alpha), sc, bt));
        v = q[24]; m = fmaxf(m, fmaf(tern_val(v, delta, alpha), sc, bt));
        v = q[25]; m = fmaxf(m, fmaf(tern_val(v, delta, alpha), sc, bt));
        g_A1[b * 9216 + cc * 288 + py * 24 + px] = fmaxf(m, 0.f);
    }
}

// ================= conv2: 4 img/block, warp = (img-pair, 16 co) =================
// 256 thr, 8 warps: ip = w>>2 selects images {2ip, 2ip+1}; cog = w&3 -> co [cog*16, cog*16+16)
// per tap: 4 lds2 (16 co weights) + 4 lds32 (x) + 4 dup + 32 FFMA2
// weights staged in 4-ci chunks (25.6KB), double buffered inside 64KB sout overlay
__global__ void __launch_bounds__(256) k_conv2(
    const float* __restrict__ bias, const float* __restrict__ bng,
    const float* __restrict__ bnb)
{
    extern __shared__ float sm[];
    float* sin_ = sm;                 // 36864 floats
    float* sov  = sm + 36864;         // 16384 floats (wbuf dbuf 2x6400 floats; later sout)
    __shared__ float sb2[64], sscale[64], sbeta[64];

    int b = blockIdx.x, tid = threadIdx.x;
    unsigned sin_u = s2u(sin_);
    unsigned sov_u = s2u(sov);

    const float* gin = g_A1 + b * 4 * 9216;
    #pragma unroll
    for (int i = 0; i < 36; i++) {
        int o = tid + i * 256;                 // 0..9215 float4 chunks
        cpasync16(sin_u + o * 16, gin + o * 4);
    }
    // stage weight chunk 0 (ci 0..3) = 6400 floats = 1600 float4
    for (int o = tid; o < 1600; o += 256)
        cpasync16(sov_u + o * 16, g_W2T + o * 4);
    CP_COMMIT();

    if (tid < 64) {
        sb2[tid]    = bias[tid];
        sscale[tid] = bng[tid] * BN_INV;
        sbeta[tid]  = bnb[tid];
    }
    CP_WAIT_ALL();
    __syncthreads();

    int w = tid >> 5, lane = tid & 31;
    int ip = w >> 2, cog = w & 3;
    int py = lane >> 3, px = lane & 7;

    ull acc[2][2][8];                         // [img-in-pair][row-half][co-pair]
    #pragma unroll
    for (int j = 0; j < 8; j++) {
        ull bvj = pk2(sb2[cog * 16 + 2 * j], sb2[cog * 16 + 2 * j + 1]);
        acc[0][0][j] = bvj; acc[0][1][j] = bvj;
        acc[1][0][j] = bvj; acc[1][1][j] = bvj;
    }

    unsigned ax0 = sin_u + (ip * 2) * 36864 + (py * 24 + px) * 4;
    unsigned ax1 = ax0 + 36864;
    unsigned wlane = cog * 64;                // 16 floats per co-group

    for (int s = 0; s < 8; s++) {
        int cur = s & 1;
        if (s < 7) {
            const float* src = g_W2T + (s + 1) * 6400;
            unsigned dst = sov_u + (cur ^ 1) * 25600;
            for (int o = tid; o < 1600; o += 256)
                cpasync16(dst + o * 16, src + o * 4);
            CP_COMMIT();
        }
        #pragma unroll
        for (int c4 = 0; c4 < 4; c4++) {
            int ci = s * 4 + c4;
            unsigned swc = sov_u + cur * 25600 + c4 * 6400 + wlane;
            unsigned a0 = ax0 + ci * 1152;
            unsigned a1 = ax1 + ci * 1152;
            #pragma unroll
            for (int t = 0; t < 25; t++) {
                const int io = ((t / 5) * 24 + (t % 5)) * 4;
                ull w01, w23, w45, w67, w89, wab, wcd, wef;
                lds2(w01, w23, swc + t * 256);
                lds2(w45, w67, swc + t * 256 + 16);
                lds2(w89, wab, swc + t * 256 + 32);
                lds2(wcd, wef, swc + t * 256 + 48);
                float x00 = lds32(a0 + io);
                float x01 = lds32(a0 + io + 384);
                float x10 = lds32(a1 + io);
                float x11 = lds32(a1 + io + 384);
                ull d;
                d = dup2(x00);
                fma2(acc[0][0][0], d, w01); fma2(acc[0][0][1], d, w23);
                fma2(acc[0][0][2], d, w45); fma2(acc[0][0][3], d, w67);
                fma2(acc[0][0][4], d, w89); fma2(acc[0][0][5], d, wab);
                fma2(acc[0][0][6], d, wcd); fma2(acc[0][0][7], d, wef);
                d = dup2(x01);
                fma2(acc[0][1][0], d, w01); fma2(acc[0][1][1], d, w23);
                fma2(acc[0][1][2], d, w45); fma2(acc[0][1][3], d, w67);
                fma2(acc[0][1][4], d, w89); fma2(acc[0][1][5], d, wab);
                fma2(acc[0][1][6], d, wcd); fma2(acc[0][1][7], d, wef);
                d = dup2(x10);
                fma2(acc[1][0][0], d, w01); fma2(acc[1][0][1], d, w23);
                fma2(acc[1][0][2], d, w45); fma2(acc[1][0][3], d, w67);
                fma2(acc[1][0][4], d, w89); fma2(acc[1][0][5], d, wab);
                fma2(acc[1][0][6], d, wcd); fma2(acc[1][0][7], d, wef);
                d = dup2(x11);
                fma2(acc[1][1][0], d, w01); fma2(acc[1][1][1], d, w23);
                fma2(acc[1][1][2], d, w45); fma2(acc[1][1][3], d, w67);
                fma2(acc[1][1][4], d, w89); fma2(acc[1][1][5], d, wab);
                fma2(acc[1][1][6], d, wcd); fma2(acc[1][1][7], d, wef);
            }
        }
        if (s < 7) { CP_WAIT_ALL(); __syncthreads(); }
    }

    // per-image stats; image img lives in warps with ip == img>>1, slot img&1
    float dlt[4], alf[4];
    #pragma unroll
    for (int img = 0; img < 4; img++) {
        float as = 0.f;
        if (ip == (img >> 1)) {
            int il = img & 1;
            #pragma unroll
            for (int pz = 0; pz < 2; pz++)
                #pragma unroll
                for (int j = 0; j < 8; j++) {
                    float lo, hi; unpk2(acc[il][pz][j], lo, hi);
                    as += fabsf(lo) + fabsf(hi);
                }
        }
        dlt[img] = 0.7f * blockReduce<8>(as) / 4096.0f;
    }
    #pragma unroll
    for (int img = 0; img < 4; img++) {
        float ms = 0.f, mc = 0.f;
        if (ip == (img >> 1)) {
            int il = img & 1;
            #pragma unroll
            for (int pz = 0; pz < 2; pz++)
                #pragma unroll
                for (int j = 0; j < 8; j++) {
                    float lo, hi; unpk2(acc[il][pz][j], lo, hi);
                    float a = fabsf(lo); if (a > dlt[img]) { ms += a; mc += 1.f; }
                    a = fabsf(hi);       if (a > dlt[img]) { ms += a; mc += 1.f; }
                }
        }
        ms = blockReduce<8>(ms);
        mc = blockReduce<8>(mc);
        alf[img] = ms / mc;
    }

    // stage conv outputs (sov reuse; weight reads done before reduction barriers)
    float* sout = sov;
    #pragma unroll
    for (int il = 0; il < 2; il++) {
        int img = ip * 2 + il;
        #pragma unroll
        for (int pz = 0; pz < 2; pz++) {
            int p = lane + pz * 32;
            #pragma unroll
            for (int j = 0; j < 8; j++) {
                float lo, hi; unpk2(acc[il][pz][j], lo, hi);
                sout[img * 4096 + (cog * 16 + 2 * j) * 64 + p]     = lo;
                sout[img * 4096 + (cog * 16 + 2 * j + 1) * 64 + p] = hi;
            }
        }
    }
    __syncthreads();

    // tern + BN + pool + relu -> g_A2 transposed [feature][image]
    for (int u = tid; u < 4096; u += 256) {
        int img = u >> 10, idx = u & 1023;
        int c = idx >> 4, p = idx & 15;
        int py2 = p >> 2, px2 = p & 3;
        const float* q = sout + img * 4096 + c * 64 + (2 * py2) * 8 + 2 * px2;
        float delta = dlt[img], alpha = alf[img];
        float sc = sscale[c], bt = sbeta[c];
        float m = -CUDART_INF_F, v;
        v = q[0]; m = fmaxf(m, fmaf(tern_val(v, delta, alpha), sc, bt));
        v = q[1]; m = fmaxf(m, fmaf(tern_val(v, delta, alpha), sc, bt));
        v = q[8]; m = fmaxf(m, fmaf(tern_val(v, delta, alpha), sc, bt));
        v = q[9]; m = fmaxf(m, fmaf(tern_val(v, delta, alpha), sc, bt));
        g_A2[idx * 2048 + b * 4 + img] = fmaxf(m, 0.f);
    }
}

// ================= fc1: R5 config (64x64 tile, grid 256) =================
__global__ void __launch_bounds__(256) k_fc1(const float* __restrict__ bias)
{
    extern __shared__ float sm[];
    float* As = sm;              // [2][32][64]
    float* Bs = sm + 4096;       // [2][32][64]

    int bn = blockIdx.x * 64, bm = blockIdx.y * 64;
    int tid = threadIdx.x, tx = tid & 15, ty = tid >> 4;
    unsigned as_u = s2u(As), bs_u = s2u(Bs);

    ull acc[4][2];
    #pragma unroll
    for (int c = 0; c < 4; c++) { acc[c][0] = 0ull; acc[c][1] = 0ull; }

    #pragma unroll
    for (int i = 0; i < 2; i++) {
        int o = tid + i * 256;                 // 0..511
        int kk = o >> 4, seg = o & 15;
        cpasync16(as_u + (kk * 64 + seg * 4) * 4, g_A2 + kk * 2048 + bm + seg * 4);
        cpasync16(bs_u + (kk * 64 + seg * 4) * 4, g_W1T + kk * 512 + bn + seg * 4);
    }
    CP_COMMIT();
    CP_WAIT_ALL();
    __syncthreads();

    for (int kc = 0; kc < 32; kc++) {
        int cur = kc & 1;
        if (kc < 31) {
            int k0 = (kc + 1) * 32, nb = cur ^ 1;
            #pragma unroll
            for (int i = 0; i < 2; i++) {
                int o = tid + i * 256;
                int kk = o >> 4, seg = o & 15;
                cpasync16(as_u + (nb * 2048 + kk * 64 + seg * 4) * 4,
                          g_A2 + (k0 + kk) * 2048 + bm + seg * 4);
                cpasync16(bs_u + (nb * 2048 + kk * 64 + seg * 4) * 4,
                          g_W1T + (k0 + kk) * 512 + bn + seg * 4);
            }
            CP_COMMIT();
        }
        unsigned ab = as_u + cur * 8192 + ty * 16;
        unsigned bb = bs_u + cur * 8192 + tx * 16;
        #pragma unroll
        for (int kk = 0; kk < 32; kk++) {
            ull a01, a23;
            lds2(a01, a23, ab + kk * 256);
            float b0, b1, b2, b3;
            lds128f(b0, b1, b2, b3, bb + kk * 256);
            ull d;
            d = dup2(b0); fma2(acc[0][0], a01, d); fma2(acc[0][1], a23, d);
            d = dup2(b1); fma2(acc[1][0], a01, d); fma2(acc[1][1], a23, d);
            d = dup2(b2); fma2(acc[2][0], a01, d); fma2(acc[2][1], a23, d);
            d = dup2(b3); fma2(acc[3][0], a01, d); fma2(acc[3][1], a23, d);
        }
        if (kc < 31) { CP_WAIT_ALL(); __syncthreads(); }
    }

    #pragma unroll
    for (int c = 0; c < 4; c++) {
        float bl = bias[bn + tx * 4 + c];
        int r0 = bm + ty * 4;
        float lo, hi;
        unpk2(acc[c][0], lo, hi);
        g_F1[r0 * 512 + bn + tx * 4 + c]       = lo + bl;
        g_F1[(r0 + 1) * 512 + bn + tx * 4 + c] = hi + bl;
        unpk2(acc[c][1], lo, hi);
        g_F1[(r0 + 2) * 512 + bn + tx * 4 + c] = lo + bl;
        g_F1[(r0 + 3) * 512 + bn + tx * 4 + c] = hi + bl;
    }
}

// ================= head (R5) =================
__global__ void __launch_bounds__(128) k_head(
    const float* __restrict__ W2, const float* __restrict__ b2,
    float* __restrict__ out)
{
    __shared__ float sh[512];
    __shared__ float so[10];

    int b = blockIdx.x, tid = threadIdx.x;
    float4 v4 = ((const float4*)(g_F1 + b * 512))[tid];
    float asum = fabsf(v4.x) + fabsf(v4.y) + fabsf(v4.z) + fabsf(v4.w);
    float tot = blockReduce<4>(asum);
    float delta = 0.7f * tot / 512.0f;

    float ms = 0.f, mc = 0.f;
    float vv[4] = {v4.x, v4.y, v4.z, v4.w};
    #pragma unroll
    for (int i = 0; i < 4; i++) {
        float a = fabsf(vv[i]);
        if (a > delta) { ms += a; mc += 1.f; }
    }
    ms = blockReduce<4>(ms);
    mc = blockReduce<4>(mc);
    float alpha = ms / mc;

    #pragma unroll
    for (int i = 0; i < 4; i++)
        sh[tid * 4 + i] = (vv[i] > delta) ? alpha : 0.f;
    __syncthreads();

    int wd = tid >> 5, ln = tid & 31;
    for (int r = wd; r < 10; r += 4) {
        float s = 0.f;
        const float* wr = W2 + r * 512;
        for (int j = ln; j < 512; j += 32) s += sh[j] * wr[j];
        #pragma unroll
        for (int o = 16; o > 0; o >>= 1) s += __shfl_xor_sync(0xFFFFFFFFu, s, o);
        if (ln == 0) so[r] = s + b2[r];
    }
    __syncthreads();

    if (tid == 0) {
        float s = 0.f;
        #pragma unroll
        for (int n = 0; n < 10; n++) s += fabsf(so[n]);
        float d2 = 0.7f * s / 10.0f;
        float ms2 = 0.f, c2 = 0.f;
        #pragma unroll
        for (int n = 0; n < 10; n++) {
            float a = fabsf(so[n]);
            if (a > d2) { ms2 += a; c2 += 1.f; }
        }
        float a2 = ms2 / c2;
        #pragma unroll
        for (int n = 0; n < 10; n++)
            out[b * 10 + n] = tern_val(so[n], d2, a2);
    }
}

// ---------------- launch ----------------
extern "C" void kernel_launch(void* const* d_in, const int* in_sizes, int n_in,
                              void* d_out, int out_size)
{
    (void)in_sizes; (void)n_in; (void)out_size;
    const float* x       = (const float*)d_in[0];
    const float* conv1_w = (const float*)d_in[1];
    const float* conv1_b = (const float*)d_in[2];
    const float* bn1_g   = (const float*)d_in[3];
    const float* bn1_b   = (const float*)d_in[4];
    const float* conv2_w = (const float*)d_in[5];
    const float* conv2_b = (const float*)d_in[6];
    const float* bn2_g   = (const float*)d_in[7];
    const float* bn2_b   = (const float*)d_in[8];
    const float* fc1_w   = (const float*)d_in[9];
    const float* fc1_b   = (const float*)d_in[10];
    const float* fc2_w   = (const float*)d_in[11];
    const float* fc2_b   = (const float*)d_in[12];
    float* out = (float*)d_out;

    const int SMEM1 = (1584 + 32 * SC1STR) * 4;          // ~80.3 KB
    const int SMEM2 = (36864 + 16384) * 4;               // 212992 B
    const int SMEMF = (4096 + 4096) * 4;                 // 32 KB
    cudaFuncSetAttribute(k_conv1, cudaFuncAttributeMaxDynamicSharedMemorySize, SMEM1);
    cudaFuncSetAttribute(k_conv2, cudaFuncAttributeMaxDynamicSharedMemorySize, SMEM2);
    cudaFuncSetAttribute(k_fc1,   cudaFuncAttributeMaxDynamicSharedMemorySize, SMEMF);

    k_pre<<<(N_W2 + N_W1 + 255) / 256, 256>>>(conv2_w, fc1_w);
    k_conv1<<<2048, 256, SMEM1>>>(x, conv1_w, conv1_b, bn1_g, bn1_b);
    k_conv2<<<512, 256, SMEM2>>>(conv2_b, bn2_g, bn2_b);
    k_fc1<<<dim3(8, 32), 256, SMEMF>>>(fc1_b);
    k_head<<<2048, 128>>>(fc2_w, fc2_b, out);
}

// round 8
// speedup vs baseline: 1.5992x; 1.0709x over previous
#include <cuda_runtime.h>
#include <cuda_bf16.h>
#include <math_constants.h>

typedef unsigned long long ull;

// ---------------- f32x2 helpers ----------------
__device__ __forceinline__ ull pk2(float lo, float hi) {
    ull r; asm("mov.b64 %0, {%1, %2};" : "=l"(r) : "f"(lo), "f"(hi)); return r;
}
__device__ __forceinline__ ull dup2(float v) {
    ull r; asm("mov.b64 %0, {%1, %1};" : "=l"(r) : "f"(v)); return r;
}
__device__ __forceinline__ void unpk2(ull v, float& lo, float& hi) {
    asm("mov.b64 {%0, %1}, %2;" : "=f"(lo), "=f"(hi) : "l"(v));
}
__device__ __forceinline__ void fma2(ull& acc, ull a, ull b) {
    asm("fma.rn.f32x2 %0, %1, %2, %0;" : "+l"(acc) : "l"(a), "l"(b));
}
__device__ __forceinline__ void lds2(ull& a, ull& b, unsigned addr) {
    asm("ld.shared.v2.u64 {%0, %1}, [%2];" : "=l"(a), "=l"(b) : "r"(addr));
}
__device__ __forceinline__ void lds128f(float& x, float& y, float& z, float& w, unsigned a) {
    asm("ld.shared.v4.f32 {%0, %1, %2, %3}, [%4];"
        : "=f"(x), "=f"(y), "=f"(z), "=f"(w) : "r"(a));
}
__device__ __forceinline__ float lds32(unsigned a) {
    float v; asm("ld.shared.f32 %0, [%1];" : "=f"(v) : "r"(a)); return v;
}
__device__ __forceinline__ void sts64(unsigned addr, ull v) {
    asm volatile("st.shared.b64 [%0], %1;" :: "r"(addr), "l"(v));
}
__device__ __forceinline__ void cpasync16(unsigned saddr, const void* g) {
    asm volatile("cp.async.ca.shared.global [%0], [%1], 16;" :: "r"(saddr), "l"(g));
}
#define CP_COMMIT()   asm volatile("cp.async.commit_group;")
#define CP_WAIT_ALL() asm volatile("cp.async.wait_group 0;")
__device__ __forceinline__ unsigned s2u(const void* p) {
    return (unsigned)__cvta_generic_to_shared(p);
}

// ---------------- scratch ----------------
__device__ __align__(16) float g_A1[2048 * 32 * 288];  // conv1 out [b][c][12 rows, stride 24]
__device__ __align__(16) float g_A2[1024 * 2048];      // conv2 out TRANSPOSED [feature k][image m]
__device__ __align__(16) float g_F1[2048 * 512];       // fc1 pre-ternarize [m][n]
__device__ __align__(16) float g_W2T[800 * 64];        // conv2 weights [k][co]
__device__ __align__(16) float g_W1T[1024 * 512];      // fc1 weights [k][n]

#define BN_INV 0.9999950000374997f

template <int NW>
__device__ __forceinline__ float blockReduce(float v) {
    __shared__ float r[NW];
    #pragma unroll
    for (int o = 16; o > 0; o >>= 1) v += __shfl_xor_sync(0xFFFFFFFFu, v, o);
    int wid = threadIdx.x >> 5, lane = threadIdx.x & 31;
    __syncthreads();
    if (lane == 0) r[wid] = v;
    __syncthreads();
    float t = 0.f;
    #pragma unroll
    for (int i = 0; i < NW; i++) t += r[i];
    return t;
}

__device__ __forceinline__ float tern_val(float v, float delta, float alpha) {
    return (v > delta) ? alpha : ((v < -delta) ? -alpha : 0.f);
}

// ---------------- k_pre: both weight transposes ----------------
#define N_W2 (64 * 800)
#define N_W1 (512 * 1024)
__global__ void k_pre(const float* __restrict__ w2, const float* __restrict__ w1) {
    int i = blockIdx.x * 256 + threadIdx.x;
    if (i < N_W2) {
        int co = i / 800, k = i % 800;
        g_W2T[k * 64 + co] = w2[i];
    } else if (i < N_W2 + N_W1) {
        int j = i - N_W2;
        int n = j / 1024, k = j % 1024;
        g_W1T[k * 512 + n] = w1[j];
    }
}

// ================= conv1 (unchanged) =================
#define SC1STR 578
__global__ void __launch_bounds__(256, 2) k_conv1(
    const float* __restrict__ x, const float* __restrict__ w,
    const float* __restrict__ bias, const float* __restrict__ bng,
    const float* __restrict__ bnb)
{
    extern __shared__ float sm[];
    float* sx  = sm;            // 784
    float* sw  = sm + 784;      // 800
    float* sc1 = sm + 1584;     // 32*578
    __shared__ float sb[32], sscale[32], sbeta[32];

    int b = blockIdx.x, tid = threadIdx.x;
    const float* xb = x + b * 784;
    for (int i = tid; i < 784; i += 256) sx[i] = xb[i];
    for (int i = tid; i < 800; i += 256) sw[i] = w[i];
    if (tid < 32) {
        sb[tid]     = bias[tid];
        sscale[tid] = bng[tid] * BN_INV;
        sbeta[tid]  = bnb[tid];
    }
    __syncthreads();

    int c = tid & 31, rg = tid >> 5;
    float wr[25];
    #pragma unroll
    for (int i = 0; i < 25; i++) wr[i] = sw[c * 25 + i];
    float bv = sb[c];

    unsigned scb = s2u(sm) + (1584 + c * SC1STR) * 4;
    float asum = 0.f;

    #pragma unroll
    for (int rr = 0; rr < 3; rr++) {
        int r = rg * 3 + rr;
        ull acc[12];
        #pragma unroll
        for (int j = 0; j < 12; j++) acc[j] = dup2(bv);

        #pragma unroll
        for (int ky = 0; ky < 5; ky++) {
            const float4* xr4 = (const float4*)(sx + (r + ky) * 28);
            float v[28];
            #pragma unroll
            for (int q = 0; q < 7; q++) {
                float4 t = xr4[q];
                v[q*4] = t.x; v[q*4+1] = t.y; v[q*4+2] = t.z; v[q*4+3] = t.w;
            }
            #pragma unroll
            for (int kx = 0; kx < 5; kx++) {
                ull wd = dup2(wr[ky * 5 + kx]);
                #pragma unroll
                for (int j = 0; j < 12; j++)
                    fma2(acc[j], pk2(v[kx + 2*j], v[kx + 2*j + 1]), wd);
            }
        }
        unsigned ro = scb + r * 24 * 4;
        #pragma unroll
        for (int j = 0; j < 12; j++) {
            sts64(ro + j * 8, acc[j]);
            float lo, hi; unpk2(acc[j], lo, hi);
            asum += fabsf(lo) + fabsf(hi);
        }
    }

    float tot = blockReduce<8>(asum);
    float delta = 0.7f * tot / 18432.0f;

    float ms = 0.f, mc = 0.f;
    #pragma unroll
    for (int rr = 0; rr < 3; rr++) {
        int r = rg * 3 + rr;
        #pragma unroll
        for (int t = 0; t < 24; t++) {
            float a = fabsf(sc1[c * SC1STR + r * 24 + t]);
            if (a > delta) { ms += a; mc += 1.f; }
        }
    }
    ms = blockReduce<8>(ms);
    mc = blockReduce<8>(mc);
    float alpha = ms / mc;

    for (int u = tid; u < 4608; u += 256) {
        int cc = u / 144, p = u % 144;
        int py = p / 12, px = p % 12;
        const float* q = sc1 + cc * SC1STR + (2 * py) * 24 + 2 * px;
        float sc = sscale[cc], bt = sbeta[cc];
        float m = -CUDART_INF_F, v;
        v = q[0];  m = fmaxf(m, fmaf(tern_val(v, delta, alpha), sc, bt));
        v = q[1];  m = fmaxf(m, fmaf(tern_val(v, delta, alpha), sc, bt));
        v = q[24]; m = fmaxf(m, fmaf(tern_val(v, delta, alpha), sc, bt));
        v = q[25]; m = fmaxf(m, fmaf(tern_val(v, delta, alpha), sc, bt));
        g_A1[b * 9216 + cc * 288 + py * 24 + px] = fmaxf(m, 0.f);
    }
}

// ================= conv2: 2 img/block, 104KB smem -> 2 CTAs/SM =================
// 256 thr, 8 warps: iw = w>>2 -> image; cog = w&3 -> co [cog*16, cog*16+16)
// per tap: 4 lds2 (16 co weights) + 2 lds32 (x) + 2 dup + 16 FFMA2
// weights in 2-ci chunks (12.8KB), double buffered; sout overlays wbuf
__global__ void __launch_bounds__(256, 2) k_conv2(
    const float* __restrict__ bias, const float* __restrict__ bng,
    const float* __restrict__ bnb)
{
    extern __shared__ float sm[];
    float* sin_ = sm;                 // 18432 floats (2 img)
    float* sov  = sm + 18432;         // 8192 floats: wbuf dbuf 2x3200 / sout 2x4096
    __shared__ float sb2[64], sscale[64], sbeta[64];

    int b = blockIdx.x, tid = threadIdx.x;
    unsigned sin_u = s2u(sin_);
    unsigned sov_u = s2u(sov);

    const float* gin = g_A1 + b * 2 * 9216;
    #pragma unroll
    for (int i = 0; i < 18; i++) {
        int o = tid + i * 256;                 // 0..4607 float4 chunks
        cpasync16(sin_u + o * 16, gin + o * 4);
    }
    // stage weight chunk 0 (ci 0..1) = 3200 floats = 800 float4
    for (int o = tid; o < 800; o += 256)
        cpasync16(sov_u + o * 16, g_W2T + o * 4);
    CP_COMMIT();

    if (tid < 64) {
        sb2[tid]    = bias[tid];
        sscale[tid] = bng[tid] * BN_INV;
        sbeta[tid]  = bnb[tid];
    }
    CP_WAIT_ALL();
    __syncthreads();

    int w = tid >> 5, lane = tid & 31;
    int iw = w >> 2, cog = w & 3;
    int py = lane >> 3, px = lane & 7;

    ull acc[2][8];                            // [row-half][co-pair]
    #pragma unroll
    for (int j = 0; j < 8; j++) {
        ull bvj = pk2(sb2[cog * 16 + 2 * j], sb2[cog * 16 + 2 * j + 1]);
        acc[0][j] = bvj; acc[1][j] = bvj;
    }

    unsigned ax = sin_u + iw * 36864 + (py * 24 + px) * 4;
    unsigned wlane = cog * 64;                // 16 floats per co-group

    for (int s = 0; s < 16; s++) {
        int cur = s & 1;
        if (s < 15) {
            const float* src = g_W2T + (s + 1) * 3200;
            unsigned dst = sov_u + (cur ^ 1) * 12800;
            for (int o = tid; o < 800; o += 256)
                cpasync16(dst + o * 16, src + o * 4);
            CP_COMMIT();
        }
        #pragma unroll
        for (int c2 = 0; c2 < 2; c2++) {
            int ci = s * 2 + c2;
            unsigned swc = sov_u + cur * 12800 + c2 * 6400 + wlane;
            unsigned a0 = ax + ci * 1152;
            #pragma unroll
            for (int t = 0; t < 25; t++) {
                const int io = ((t / 5) * 24 + (t % 5)) * 4;
                ull w01, w23, w45, w67, w89, wab, wcd, wef;
                lds2(w01, w23, swc + t * 256);
                lds2(w45, w67, swc + t * 256 + 16);
                lds2(w89, wab, swc + t * 256 + 32);
                lds2(wcd, wef, swc + t * 256 + 48);
                float x0 = lds32(a0 + io);
                float x1 = lds32(a0 + io + 384);
                ull d;
                d = dup2(x0);
                fma2(acc[0][0], d, w01); fma2(acc[0][1], d, w23);
                fma2(acc[0][2], d, w45); fma2(acc[0][3], d, w67);
                fma2(acc[0][4], d, w89); fma2(acc[0][5], d, wab);
                fma2(acc[0][6], d, wcd); fma2(acc[0][7], d, wef);
                d = dup2(x1);
                fma2(acc[1][0], d, w01); fma2(acc[1][1], d, w23);
                fma2(acc[1][2], d, w45); fma2(acc[1][3], d, w67);
                fma2(acc[1][4], d, w89); fma2(acc[1][5], d, wab);
                fma2(acc[1][6], d, wcd); fma2(acc[1][7], d, wef);
            }
        }
        if (s < 15) { CP_WAIT_ALL(); __syncthreads(); }
    }

    // per-image stats; image img owned by warps with iw == img
    float dlt[2], alf[2];
    #pragma unroll
    for (int img = 0; img < 2; img++) {
        float as = 0.f;
        if (iw == img) {
            #pragma unroll
            for (int pz = 0; pz < 2; pz++)
                #pragma unroll
                for (int j = 0; j < 8; j++) {
                    float lo, hi; unpk2(acc[pz][j], lo, hi);
                    as += fabsf(lo) + fabsf(hi);
                }
        }
        dlt[img] = 0.7f * blockReduce<8>(as) / 4096.0f;
    }
    #pragma unroll
    for (int img = 0; img < 2; img++) {
        float ms = 0.f, mc = 0.f;
        if (iw == img) {
            #pragma unroll
            for (int pz = 0; pz < 2; pz++)
                #pragma unroll
                for (int j = 0; j < 8; j++) {
                    float lo, hi; unpk2(acc[pz][j], lo, hi);
                    float a = fabsf(lo); if (a > dlt[img]) { ms += a; mc += 1.f; }
                    a = fabsf(hi);       if (a > dlt[img]) { ms += a; mc += 1.f; }
                }
        }
        ms = blockReduce<8>(ms);
        mc = blockReduce<8>(mc);
        alf[img] = ms / mc;
    }

    // stage conv outputs (sov reuse; weight reads done before reduction barriers)
    float* sout = sov;
    #pragma unroll
    for (int pz = 0; pz < 2; pz++) {
        int p = lane + pz * 32;
        #pragma unroll
        for (int j = 0; j < 8; j++) {
            float lo, hi; unpk2(acc[pz][j], lo, hi);
            sout[iw * 4096 + (cog * 16 + 2 * j) * 64 + p]     = lo;
            sout[iw * 4096 + (cog * 16 + 2 * j + 1) * 64 + p] = hi;
        }
    }
    __syncthreads();

    // tern + BN + pool + relu -> g_A2 transposed [feature][image]
    for (int u = tid; u < 2048; u += 256) {
        int img = u >> 10, idx = u & 1023;
        int c = idx >> 4, p = idx & 15;
        int py2 = p >> 2, px2 = p & 3;
        const float* q = sout + img * 4096 + c * 64 + (2 * py2) * 8 + 2 * px2;
        float delta = dlt[img], alpha = alf[img];
        float sc = sscale[c], bt = sbeta[c];
        float m = -CUDART_INF_F, v;
        v = q[0]; m = fmaxf(m, fmaf(tern_val(v, delta, alpha), sc, bt));
        v = q[1]; m = fmaxf(m, fmaf(tern_val(v, delta, alpha), sc, bt));
        v = q[8]; m = fmaxf(m, fmaf(tern_val(v, delta, alpha), sc, bt));
        v = q[9]; m = fmaxf(m, fmaf(tern_val(v, delta, alpha), sc, bt));
        g_A2[idx * 2048 + b * 2 + img] = fmaxf(m, 0.f);
    }
}

// ================= fc1: 64x128 tile, 128 thr, 8x8 micro (smem-balanced) =================
// grid (4, 32); tx = tid&15 -> 8 cols, ty = tid>>4 -> 8 rows
__global__ void __launch_bounds__(128) k_fc1(const float* __restrict__ bias)
{
    extern __shared__ float sm[];
    float* As = sm;              // [2][32][64]  16KB
    float* Bs = sm + 4096;       // [2][32][128] 32KB

    int bn = blockIdx.x * 128, bm = blockIdx.y * 64;
    int tid = threadIdx.x, tx = tid & 15, ty = tid >> 4;
    unsigned as_u = s2u(As), bs_u = s2u(Bs);

    ull acc[8][4];
    #pragma unroll
    for (int c = 0; c < 8; c++)
        #pragma unroll
        for (int rp = 0; rp < 4; rp++) acc[c][rp] = 0ull;

    // stage chunk 0: A 512 float4, B 1024 float4
    #pragma unroll
    for (int i = 0; i < 4; i++) {
        int o = tid + i * 128;                 // 0..511
        int kk = o >> 4, seg = o & 15;
        cpasync16(as_u + (kk * 64 + seg * 4) * 4, g_A2 + kk * 2048 + bm + seg * 4);
    }
    #pragma unroll
    for (int i = 0; i < 8; i++) {
        int o = tid + i * 128;                 // 0..1023
        int kk = o >> 5, seg = o & 31;
        cpasync16(bs_u + (kk * 128 + seg * 4) * 4, g_W1T + kk * 512 + bn + seg * 4);
    }
    CP_COMMIT();
    CP_WAIT_ALL();
    __syncthreads();

    for (int kc = 0; kc < 32; kc++) {
        int cur = kc & 1;
        if (kc < 31) {
            int k0 = (kc + 1) * 32, nb = cur ^ 1;
            #pragma unroll
            for (int i = 0; i < 4; i++) {
                int o = tid + i * 128;
                int kk = o >> 4, seg = o & 15;
                cpasync16(as_u + (nb * 2048 + kk * 64 + seg * 4) * 4,
                          g_A2 + (k0 + kk) * 2048 + bm + seg * 4);
            }
            #pragma unroll
            for (int i = 0; i < 8; i++) {
                int o = tid + i * 128;
                int kk = o >> 5, seg = o & 31;
                cpasync16(bs_u + (nb * 4096 + kk * 128 + seg * 4) * 4,
                          g_W1T + (k0 + kk) * 512 + bn + seg * 4);
            }
            CP_COMMIT();
        }
        unsigned ab = as_u + cur * 8192 + ty * 32;     // ty*8 floats
        unsigned bb = bs_u + cur * 16384 + tx * 32;    // tx*8 floats
        #pragma unroll
        for (int kk = 0; kk < 32; kk++) {
            ull a01, a23, a45, a67;
            lds2(a01, a23, ab + kk * 256);
            lds2(a45, a67, ab + kk * 256 + 16);
            float b0, b1, b2, b3, b4, b5, b6, b7;
            lds128f(b0, b1, b2, b3, bb + kk * 512);
            lds128f(b4, b5, b6, b7, bb + kk * 512 + 16);
            ull d;
            d = dup2(b0);
            fma2(acc[0][0], a01, d); fma2(acc[0][1], a23, d);
            fma2(acc[0][2], a45, d); fma2(acc[0][3], a67, d);
            d = dup2(b1);
            fma2(acc[1][0], a01, d); fma2(acc[1][1], a23, d);
            fma2(acc[1][2], a45, d); fma2(acc[1][3], a67, d);
            d = dup2(b2);
            fma2(acc[2][0], a01, d); fma2(acc[2][1], a23, d);
            fma2(acc[2][2], a45, d); fma2(acc[2][3], a67, d);
            d = dup2(b3);
            fma2(acc[3][0], a01, d); fma2(acc[3][1], a23, d);
            fma2(acc[3][2], a45, d); fma2(acc[3][3], a67, d);
            d = dup2(b4);
            fma2(acc[4][0], a01, d); fma2(acc[4][1], a23, d);
            fma2(acc[4][2], a45, d); fma2(acc[4][3], a67, d);
            d = dup2(b5);
            fma2(acc[5][0], a01, d); fma2(acc[5][1], a23, d);
            fma2(acc[5][2], a45, d); fma2(acc[5][3], a67, d);
            d = dup2(b6);
            fma2(acc[6][0], a01, d); fma2(acc[6][1], a23, d);
            fma2(acc[6][2], a45, d); fma2(acc[6][3], a67, d);
            d = dup2(b7);
            fma2(acc[7][0], a01, d); fma2(acc[7][1], a23, d);
            fma2(acc[7][2], a45, d); fma2(acc[7][3], a67, d);
        }
        if (kc < 31) { CP_WAIT_ALL(); __syncthreads(); }
    }

    #pragma unroll
    for (int c = 0; c < 8; c++) {
        int col = bn + tx * 8 + c;
        float bl = bias[col];
        #pragma unroll
        for (int rp = 0; rp < 4; rp++) {
            int r = bm + ty * 8 + rp * 2;
            float lo, hi; unpk2(acc[c][rp], lo, hi);
            g_F1[r * 512 + col]       = lo + bl;
            g_F1[(r + 1) * 512 + col] = hi + bl;
        }
    }
}

// ================= head (unchanged) =================
__global__ void __launch_bounds__(128) k_head(
    const float* __restrict__ W2, const float* __restrict__ b2,
    float* __restrict__ out)
{
    __shared__ float sh[512];
    __shared__ float so[10];

    int b = blockIdx.x, tid = threadIdx.x;
    float4 v4 = ((const float4*)(g_F1 + b * 512))[tid];
    float asum = fabsf(v4.x) + fabsf(v4.y) + fabsf(v4.z) + fabsf(v4.w);
    float tot = blockReduce<4>(asum);
    float delta = 0.7f * tot / 512.0f;

    float ms = 0.f, mc = 0.f;
    float vv[4] = {v4.x, v4.y, v4.z, v4.w};
    #pragma unroll
    for (int i = 0; i < 4; i++) {
        float a = fabsf(vv[i]);
        if (a > delta) { ms += a; mc += 1.f; }
    }
    ms = blockReduce<4>(ms);
    mc = blockReduce<4>(mc);
    float alpha = ms / mc;

    #pragma unroll
    for (int i = 0; i < 4; i++)
        sh[tid * 4 + i] = (vv[i] > delta) ? alpha : 0.f;
    __syncthreads();

    int wd = tid >> 5, ln = tid & 31;
    for (int r = wd; r < 10; r += 4) {
        float s = 0.f;
        const float* wr = W2 + r * 512;
        for (int j = ln; j < 512; j += 32) s += sh[j] * wr[j];
        #pragma unroll
        for (int o = 16; o > 0; o >>= 1) s += __shfl_xor_sync(0xFFFFFFFFu, s, o);
        if (ln == 0) so[r] = s + b2[r];
    }
    __syncthreads();

    if (tid == 0) {
        float s = 0.f;
        #pragma unroll
        for (int n = 0; n < 10; n++) s += fabsf(so[n]);
        float d2 = 0.7f * s / 10.0f;
        float ms2 = 0.f, c2 = 0.f;
        #pragma unroll
        for (int n = 0; n < 10; n++) {
            float a = fabsf(so[n]);
            if (a > d2) { ms2 += a; c2 += 1.f; }
        }
        float a2 = ms2 / c2;
        #pragma unroll
        for (int n = 0; n < 10; n++)
            out[b * 10 + n] = tern_val(so[n], d2, a2);
    }
}

// ---------------- launch ----------------
extern "C" void kernel_launch(void* const* d_in, const int* in_sizes, int n_in,
                              void* d_out, int out_size)
{
    (void)in_sizes; (void)n_in; (void)out_size;
    const float* x       = (const float*)d_in[0];
    const float* conv1_w = (const float*)d_in[1];
    const float* conv1_b = (const float*)d_in[2];
    const float* bn1_g   = (const float*)d_in[3];
    const float* bn1_b   = (const float*)d_in[4];
    const float* conv2_w = (const float*)d_in[5];
    const float* conv2_b = (const float*)d_in[6];
    const float* bn2_g   = (const float*)d_in[7];
    const float* bn2_b   = (const float*)d_in[8];
    const float* fc1_w   = (const float*)d_in[9];
    const float* fc1_b   = (const float*)d_in[10];
    const float* fc2_w   = (const float*)d_in[11];
    const float* fc2_b   = (const float*)d_in[12];
    float* out = (float*)d_out;

    const int SMEM1 = (1584 + 32 * SC1STR) * 4;          // ~80.3 KB
    const int SMEM2 = (18432 + 8192) * 4;                // 106.5 KB -> 2 CTAs/SM
    const int SMEMF = (4096 + 8192) * 4;                 // 48 KB
    cudaFuncSetAttribute(k_conv1, cudaFuncAttributeMaxDynamicSharedMemorySize, SMEM1);
    cudaFuncSetAttribute(k_conv2, cudaFuncAttributeMaxDynamicSharedMemorySize, SMEM2);
    cudaFuncSetAttribute(k_fc1,   cudaFuncAttributeMaxDynamicSharedMemorySize, SMEMF);

    k_pre<<<(N_W2 + N_W1 + 255) / 256, 256>>>(conv2_w, fc1_w);
    k_conv1<<<2048, 256, SMEM1>>>(x, conv1_w, conv1_b, bn1_g, bn1_b);
    k_conv2<<<1024, 256, SMEM2>>>(conv2_b, bn2_g, bn2_b);
    k_fc1<<<dim3(4, 32), 128, SMEMF>>>(fc1_b);
    k_head<<<2048, 128>>>(fc2_w, fc2_b, out);
}

// round 9
// speedup vs baseline: 1.6363x; 1.0232x over previous
#include <cuda_runtime.h>
#include <cuda_bf16.h>
#include <math_constants.h>

typedef unsigned long long ull;

// ---------------- f32x2 helpers ----------------
__device__ __forceinline__ ull pk2(float lo, float hi) {
    ull r; asm("mov.b64 %0, {%1, %2};" : "=l"(r) : "f"(lo), "f"(hi)); return r;
}
__device__ __forceinline__ ull dup2(float v) {
    ull r; asm("mov.b64 %0, {%1, %1};" : "=l"(r) : "f"(v)); return r;
}
__device__ __forceinline__ void unpk2(ull v, float& lo, float& hi) {
    asm("mov.b64 {%0, %1}, %2;" : "=f"(lo), "=f"(hi) : "l"(v));
}
__device__ __forceinline__ void fma2(ull& acc, ull a, ull b) {
    asm("fma.rn.f32x2 %0, %1, %2, %0;" : "+l"(acc) : "l"(a), "l"(b));
}
__device__ __forceinline__ void lds2(ull& a, ull& b, unsigned addr) {
    asm("ld.shared.v2.u64 {%0, %1}, [%2];" : "=l"(a), "=l"(b) : "r"(addr));
}
__device__ __forceinline__ void lds128f(float& x, float& y, float& z, float& w, unsigned a) {
    asm("ld.shared.v4.f32 {%0, %1, %2, %3}, [%4];"
        : "=f"(x), "=f"(y), "=f"(z), "=f"(w) : "r"(a));
}
__device__ __forceinline__ float lds32(unsigned a) {
    float v; asm("ld.shared.f32 %0, [%1];" : "=f"(v) : "r"(a)); return v;
}
__device__ __forceinline__ void sts64(unsigned addr, ull v) {
    asm volatile("st.shared.b64 [%0], %1;" :: "r"(addr), "l"(v));
}
__device__ __forceinline__ void cpasync16(unsigned saddr, const void* g) {
    asm volatile("cp.async.ca.shared.global [%0], [%1], 16;" :: "r"(saddr), "l"(g));
}
#define CP_COMMIT()   asm volatile("cp.async.commit_group;")
#define CP_WAIT_ALL() asm volatile("cp.async.wait_group 0;")
__device__ __forceinline__ unsigned s2u(const void* p) {
    return (unsigned)__cvta_generic_to_shared(p);
}

// ---------------- scratch ----------------
__device__ __align__(16) float g_A1[2048 * 32 * 288];  // conv1 out [b][c][12 rows, stride 24]
__device__ __align__(16) float g_A2[1024 * 2048];      // conv2 out TRANSPOSED [feature k][image m]
__device__ __align__(16) float g_F1[2048 * 512];       // fc1 partial (K 0..511)
__device__ __align__(16) float g_F1b[2048 * 512];      // fc1 partial (K 512..1023)
__device__ __align__(16) float g_W2T[800 * 64];        // conv2 weights [k][co]
__device__ __align__(16) float g_W1T[1024 * 512];      // fc1 weights [k][n]

#define BN_INV 0.9999950000374997f

template <int NW>
__device__ __forceinline__ float blockReduce(float v) {
    __shared__ float r[NW];
    #pragma unroll
    for (int o = 16; o > 0; o >>= 1) v += __shfl_xor_sync(0xFFFFFFFFu, v, o);
    int wid = threadIdx.x >> 5, lane = threadIdx.x & 31;
    __syncthreads();
    if (lane == 0) r[wid] = v;
    __syncthreads();
    float t = 0.f;
    #pragma unroll
    for (int i = 0; i < NW; i++) t += r[i];
    return t;
}

__device__ __forceinline__ float tern_val(float v, float delta, float alpha) {
    return (v > delta) ? alpha : ((v < -delta) ? -alpha : 0.f);
}

// ---------------- k_pre: both weight transposes ----------------
#define N_W2 (64 * 800)
#define N_W1 (512 * 1024)
__global__ void k_pre(const float* __restrict__ w2, const float* __restrict__ w1) {
    int i = blockIdx.x * 256 + threadIdx.x;
    if (i < N_W2) {
        int co = i / 800, k = i % 800;
        g_W2T[k * 64 + co] = w2[i];
    } else if (i < N_W2 + N_W1) {
        int j = i - N_W2;
        int n = j / 1024, k = j % 1024;
        g_W1T[k * 512 + n] = w1[j];
    }
}

// ================= conv1 (unchanged) =================
#define SC1STR 578
__global__ void __launch_bounds__(256, 2) k_conv1(
    const float* __restrict__ x, const float* __restrict__ w,
    const float* __restrict__ bias, const float* __restrict__ bng,
    const float* __restrict__ bnb)
{
    extern __shared__ float sm[];
    float* sx  = sm;            // 784
    float* sw  = sm + 784;      // 800
    float* sc1 = sm + 1584;     // 32*578
    __shared__ float sb[32], sscale[32], sbeta[32];

    int b = blockIdx.x, tid = threadIdx.x;
    const float* xb = x + b * 784;
    for (int i = tid; i < 784; i += 256) sx[i] = xb[i];
    for (int i = tid; i < 800; i += 256) sw[i] = w[i];
    if (tid < 32) {
        sb[tid]     = bias[tid];
        sscale[tid] = bng[tid] * BN_INV;
        sbeta[tid]  = bnb[tid];
    }
    __syncthreads();

    int c = tid & 31, rg = tid >> 5;
    float wr[25];
    #pragma unroll
    for (int i = 0; i < 25; i++) wr[i] = sw[c * 25 + i];
    float bv = sb[c];

    unsigned scb = s2u(sm) + (1584 + c * SC1STR) * 4;
    float asum = 0.f;

    #pragma unroll
    for (int rr = 0; rr < 3; rr++) {
        int r = rg * 3 + rr;
        ull acc[12];
        #pragma unroll
        for (int j = 0; j < 12; j++) acc[j] = dup2(bv);

        #pragma unroll
        for (int ky = 0; ky < 5; ky++) {
            const float4* xr4 = (const float4*)(sx + (r + ky) * 28);
            float v[28];
            #pragma unroll
            for (int q = 0; q < 7; q++) {
                float4 t = xr4[q];
                v[q*4] = t.x; v[q*4+1] = t.y; v[q*4+2] = t.z; v[q*4+3] = t.w;
            }
            #pragma unroll
            for (int kx = 0; kx < 5; kx++) {
                ull wd = dup2(wr[ky * 5 + kx]);
                #pragma unroll
                for (int j = 0; j < 12; j++)
                    fma2(acc[j], pk2(v[kx + 2*j], v[kx + 2*j + 1]), wd);
            }
        }
        unsigned ro = scb + r * 24 * 4;
        #pragma unroll
        for (int j = 0; j < 12; j++) {
            sts64(ro + j * 8, acc[j]);
            float lo, hi; unpk2(acc[j], lo, hi);
            asum += fabsf(lo) + fabsf(hi);
        }
    }

    float tot = blockReduce<8>(asum);
    float delta = 0.7f * tot / 18432.0f;

    float ms = 0.f, mc = 0.f;
    #pragma unroll
    for (int rr = 0; rr < 3; rr++) {
        int r = rg * 3 + rr;
        #pragma unroll
        for (int t = 0; t < 24; t++) {
            float a = fabsf(sc1[c * SC1STR + r * 24 + t]);
            if (a > delta) { ms += a; mc += 1.f; }
        }
    }
    ms = blockReduce<8>(ms);
    mc = blockReduce<8>(mc);
    float alpha = ms / mc;

    for (int u = tid; u < 4608; u += 256) {
        int cc = u / 144, p = u % 144;
        int py = p / 12, px = p % 12;
        const float* q = sc1 + cc * SC1STR + (2 * py) * 24 + 2 * px;
        float sc = sscale[cc], bt = sbeta[cc];
        float m = -CUDART_INF_F, v;
        v = q[0];  m = fmaxf(m, fmaf(tern_val(v, delta, alpha), sc, bt));
        v = q[1];  m = fmaxf(m, fmaf(tern_val(v, delta, alpha), sc, bt));
        v = q[24]; m = fmaxf(m, fmaf(tern_val(v, delta, alpha), sc, bt));
        v = q[25]; m = fmaxf(m, fmaf(tern_val(v, delta, alpha), sc, bt));
        g_A1[b * 9216 + cc * 288 + py * 24 + px] = fmaxf(m, 0.f);
    }
}

// ================= conv2 (R8, unchanged): 2 img/block, 2 CTAs/SM =================
__global__ void __launch_bounds__(256, 2) k_conv2(
    const float* __restrict__ bias, const float* __restrict__ bng,
    const float* __restrict__ bnb)
{
    extern __shared__ float sm[];
    float* sin_ = sm;                 // 18432 floats (2 img)
    float* sov  = sm + 18432;         // 8192 floats: wbuf dbuf 2x3200 / sout 2x4096
    __shared__ float sb2[64], sscale[64], sbeta[64];

    int b = blockIdx.x, tid = threadIdx.x;
    unsigned sin_u = s2u(sin_);
    unsigned sov_u = s2u(sov);

    const float* gin = g_A1 + b * 2 * 9216;
    #pragma unroll
    for (int i = 0; i < 18; i++) {
        int o = tid + i * 256;                 // 0..4607 float4 chunks
        cpasync16(sin_u + o * 16, gin + o * 4);
    }
    for (int o = tid; o < 800; o += 256)
        cpasync16(sov_u + o * 16, g_W2T + o * 4);
    CP_COMMIT();

    if (tid < 64) {
        sb2[tid]    = bias[tid];
        sscale[tid] = bng[tid] * BN_INV;
        sbeta[tid]  = bnb[tid];
    }
    CP_WAIT_ALL();
    __syncthreads();

    int w = tid >> 5, lane = tid & 31;
    int iw = w >> 2, cog = w & 3;
    int py = lane >> 3, px = lane & 7;

    ull acc[2][8];                            // [row-half][co-pair]
    #pragma unroll
    for (int j = 0; j < 8; j++) {
        ull bvj = pk2(sb2[cog * 16 + 2 * j], sb2[cog * 16 + 2 * j + 1]);
        acc[0][j] = bvj; acc[1][j] = bvj;
    }

    unsigned ax = sin_u + iw * 36864 + (py * 24 + px) * 4;
    unsigned wlane = cog * 64;                // 16 floats per co-group

    for (int s = 0; s < 16; s++) {
        int cur = s & 1;
        if (s < 15) {
            const float* src = g_W2T + (s + 1) * 3200;
            unsigned dst = sov_u + (cur ^ 1) * 12800;
            for (int o = tid; o < 800; o += 256)
                cpasync16(dst + o * 16, src + o * 4);
            CP_COMMIT();
        }
        #pragma unroll
        for (int c2 = 0; c2 < 2; c2++) {
            int ci = s * 2 + c2;
            unsigned swc = sov_u + cur * 12800 + c2 * 6400 + wlane;
            unsigned a0 = ax + ci * 1152;
            #pragma unroll
            for (int t = 0; t < 25; t++) {
                const int io = ((t / 5) * 24 + (t % 5)) * 4;
                ull w01, w23, w45, w67, w89, wab, wcd, wef;
                lds2(w01, w23, swc + t * 256);
                lds2(w45, w67, swc + t * 256 + 16);
                lds2(w89, wab, swc + t * 256 + 32);
                lds2(wcd, wef, swc + t * 256 + 48);
                float x0 = lds32(a0 + io);
                float x1 = lds32(a0 + io + 384);
                ull d;
                d = dup2(x0);
                fma2(acc[0][0], d, w01); fma2(acc[0][1], d, w23);
                fma2(acc[0][2], d, w45); fma2(acc[0][3], d, w67);
                fma2(acc[0][4], d, w89); fma2(acc[0][5], d, wab);
                fma2(acc[0][6], d, wcd); fma2(acc[0][7], d, wef);
                d = dup2(x1);
                fma2(acc[1][0], d, w01); fma2(acc[1][1], d, w23);
                fma2(acc[1][2], d, w45); fma2(acc[1][3], d, w67);
                fma2(acc[1][4], d, w89); fma2(acc[1][5], d, wab);
                fma2(acc[1][6], d, wcd); fma2(acc[1][7], d, wef);
            }
        }
        if (s < 15) { CP_WAIT_ALL(); __syncthreads(); }
    }

    float dlt[2], alf[2];
    #pragma unroll
    for (int img = 0; img < 2; img++) {
        float as = 0.f;
        if (iw == img) {
            #pragma unroll
            for (int pz = 0; pz < 2; pz++)
                #pragma unroll
                for (int j = 0; j < 8; j++) {
                    float lo, hi; unpk2(acc[pz][j], lo, hi);
                    as += fabsf(lo) + fabsf(hi);
                }
        }
        dlt[img] = 0.7f * blockReduce<8>(as) / 4096.0f;
    }
    #pragma unroll
    for (int img = 0; img < 2; img++) {
        float ms = 0.f, mc = 0.f;
        if (iw == img) {
            #pragma unroll
            for (int pz = 0; pz < 2; pz++)
                #pragma unroll
                for (int j = 0; j < 8; j++) {
                    float lo, hi; unpk2(acc[pz][j], lo, hi);
                    float a = fabsf(lo); if (a > dlt[img]) { ms += a; mc += 1.f; }
                    a = fabsf(hi);       if (a > dlt[img]) { ms += a; mc += 1.f; }
                }
        }
        ms = blockReduce<8>(ms);
        mc = blockReduce<8>(mc);
        alf[img] = ms / mc;
    }

    float* sout = sov;
    #pragma unroll
    for (int pz = 0; pz < 2; pz++) {
        int p = lane + pz * 32;
        #pragma unroll
        for (int j = 0; j < 8; j++) {
            float lo, hi; unpk2(acc[pz][j], lo, hi);
            sout[iw * 4096 + (cog * 16 + 2 * j) * 64 + p]     = lo;
            sout[iw * 4096 + (cog * 16 + 2 * j + 1) * 64 + p] = hi;
        }
    }
    __syncthreads();

    for (int u = tid; u < 2048; u += 256) {
        int img = u >> 10, idx = u & 1023;
        int c = idx >> 4, p = idx & 15;
        int py2 = p >> 2, px2 = p & 3;
        const float* q = sout + img * 4096 + c * 64 + (2 * py2) * 8 + 2 * px2;
        float delta = dlt[img], alpha = alf[img];
        float sc = sscale[c], bt = sbeta[c];
        float m = -CUDART_INF_F, v;
        v = q[0]; m = fmaxf(m, fmaf(tern_val(v, delta, alpha), sc, bt));
        v = q[1]; m = fmaxf(m, fmaf(tern_val(v, delta, alpha), sc, bt));
        v = q[8]; m = fmaxf(m, fmaf(tern_val(v, delta, alpha), sc, bt));
        v = q[9]; m = fmaxf(m, fmaf(tern_val(v, delta, alpha), sc, bt));
        g_A2[idx * 2048 + b * 2 + img] = fmaxf(m, 0.f);
    }
}

// ================= fc1: 64x128 tile, 128 thr, 8x8 micro, K-split z=2 =================
// grid (4, 32, 2); per-CTA K=512; partials to g_F1 / g_F1b
__global__ void __launch_bounds__(128) k_fc1()
{
    extern __shared__ float sm[];
    float* As = sm;              // [2][32][64]  16KB
    float* Bs = sm + 4096;       // [2][32][128] 32KB

    int bn = blockIdx.x * 128, bm = blockIdx.y * 64;
    int kbase = blockIdx.z * 512;
    int tid = threadIdx.x, tx = tid & 15, ty = tid >> 4;
    unsigned as_u = s2u(As), bs_u = s2u(Bs);

    ull acc[8][4];
    #pragma unroll
    for (int c = 0; c < 8; c++)
        #pragma unroll
        for (int rp = 0; rp < 4; rp++) acc[c][rp] = 0ull;

    // stage chunk 0: A 512 float4, B 1024 float4
    #pragma unroll
    for (int i = 0; i < 4; i++) {
        int o = tid + i * 128;                 // 0..511
        int kk = o >> 4, seg = o & 15;
        cpasync16(as_u + (kk * 64 + seg * 4) * 4, g_A2 + (kbase + kk) * 2048 + bm + seg * 4);
    }
    #pragma unroll
    for (int i = 0; i < 8; i++) {
        int o = tid + i * 128;                 // 0..1023
        int kk = o >> 5, seg = o & 31;
        cpasync16(bs_u + (kk * 128 + seg * 4) * 4, g_W1T + (kbase + kk) * 512 + bn + seg * 4);
    }
    CP_COMMIT();
    CP_WAIT_ALL();
    __syncthreads();

    for (int kc = 0; kc < 16; kc++) {
        int cur = kc & 1;
        if (kc < 15) {
            int k0 = kbase + (kc + 1) * 32, nb = cur ^ 1;
            #pragma unroll
            for (int i = 0; i < 4; i++) {
                int o = tid + i * 128;
                int kk = o >> 4, seg = o & 15;
                cpasync16(as_u + (nb * 2048 + kk * 64 + seg * 4) * 4,
                          g_A2 + (k0 + kk) * 2048 + bm + seg * 4);
            }
            #pragma unroll
            for (int i = 0; i < 8; i++) {
                int o = tid + i * 128;
                int kk = o >> 5, seg = o & 31;
                cpasync16(bs_u + (nb * 4096 + kk * 128 + seg * 4) * 4,
                          g_W1T + (k0 + kk) * 512 + bn + seg * 4);
            }
            CP_COMMIT();
        }
        unsigned ab = as_u + cur * 8192 + ty * 32;     // ty*8 floats
        unsigned bb = bs_u + cur * 16384 + tx * 32;    // tx*8 floats
        #pragma unroll
        for (int kk = 0; kk < 32; kk++) {
            ull a01, a23, a45, a67;
            lds2(a01, a23, ab + kk * 256);
            lds2(a45, a67, ab + kk * 256 + 16);
            float b0, b1, b2, b3, b4, b5, b6, b7;
            lds128f(b0, b1, b2, b3, bb + kk * 512);
            lds128f(b4, b5, b6, b7, bb + kk * 512 + 16);
            ull d;
            d = dup2(b0);
            fma2(acc[0][0], a01, d); fma2(acc[0][1], a23, d);
            fma2(acc[0][2], a45, d); fma2(acc[0][3], a67, d);
            d = dup2(b1);
            fma2(acc[1][0], a01, d); fma2(acc[1][1], a23, d);
            fma2(acc[1][2], a45, d); fma2(acc[1][3], a67, d);
            d = dup2(b2);
            fma2(acc[2][0], a01, d); fma2(acc[2][1], a23, d);
            fma2(acc[2][2], a45, d); fma2(acc[2][3], a67, d);
            d = dup2(b3);
            fma2(acc[3][0], a01, d); fma2(acc[3][1], a23, d);
            fma2(acc[3][2], a45, d); fma2(acc[3][3], a67, d);
            d = dup2(b4);
            fma2(acc[4][0], a01, d); fma2(acc[4][1], a23, d);
            fma2(acc[4][2], a45, d); fma2(acc[4][3], a67, d);
            d = dup2(b5);
            fma2(acc[5][0], a01, d); fma2(acc[5][1], a23, d);
            fma2(acc[5][2], a45, d); fma2(acc[5][3], a67, d);
            d = dup2(b6);
            fma2(acc[6][0], a01, d); fma2(acc[6][1], a23, d);
            fma2(acc[6][2], a45, d); fma2(acc[6][3], a67, d);
            d = dup2(b7);
            fma2(acc[7][0], a01, d); fma2(acc[7][1], a23, d);
            fma2(acc[7][2], a45, d); fma2(acc[7][3], a67, d);
        }
        if (kc < 15) { CP_WAIT_ALL(); __syncthreads(); }
    }

    float* dst = blockIdx.z ? g_F1b : g_F1;
    #pragma unroll
    for (int c = 0; c < 8; c++) {
        int col = bn + tx * 8 + c;
        #pragma unroll
        for (int rp = 0; rp < 4; rp++) {
            int r = bm + ty * 8 + rp * 2;
            float lo, hi; unpk2(acc[c][rp], lo, hi);
            dst[r * 512 + col]       = lo;
            dst[(r + 1) * 512 + col] = hi;
        }
    }
}

// ================= head: sum partials + bias, tern+relu -> fc2 -> tern =================
__global__ void __launch_bounds__(128) k_head(
    const float* __restrict__ b1, const float* __restrict__ W2,
    const float* __restrict__ b2, float* __restrict__ out)
{
    __shared__ float sh[512];
    __shared__ float so[10];

    int b = blockIdx.x, tid = threadIdx.x;
    float4 va = ((const float4*)(g_F1  + b * 512))[tid];
    float4 vb = ((const float4*)(g_F1b + b * 512))[tid];
    float4 bi = ((const float4*)b1)[tid];
    float vv[4];
    vv[0] = va.x + vb.x + bi.x;
    vv[1] = va.y + vb.y + bi.y;
    vv[2] = va.z + vb.z + bi.z;
    vv[3] = va.w + vb.w + bi.w;

    float asum = fabsf(vv[0]) + fabsf(vv[1]) + fabsf(vv[2]) + fabsf(vv[3]);
    float tot = blockReduce<4>(asum);
    float delta = 0.7f * tot / 512.0f;

    float ms = 0.f, mc = 0.f;
    #pragma unroll
    for (int i = 0; i < 4; i++) {
        float a = fabsf(vv[i]);
        if (a > delta) { ms += a; mc += 1.f; }
    }
    ms = blockReduce<4>(ms);
    mc = blockReduce<4>(mc);
    float alpha = ms / mc;

    #pragma unroll
    for (int i = 0; i < 4; i++)
        sh[tid * 4 + i] = (vv[i] > delta) ? alpha : 0.f;
    __syncthreads();

    int wd = tid >> 5, ln = tid & 31;
    for (int r = wd; r < 10; r += 4) {
        float s = 0.f;
        const float* wr = W2 + r * 512;
        for (int j = ln; j < 512; j += 32) s += sh[j] * wr[j];
        #pragma unroll
        for (int o = 16; o > 0; o >>= 1) s += __shfl_xor_sync(0xFFFFFFFFu, s, o);
        if (ln == 0) so[r] = s + b2[r];
    }
    __syncthreads();

    if (tid == 0) {
        float s = 0.f;
        #pragma unroll
        for (int n = 0; n < 10; n++) s += fabsf(so[n]);
        float d2 = 0.7f * s / 10.0f;
        float ms2 = 0.f, c2 = 0.f;
        #pragma unroll
        for (int n = 0; n < 10; n++) {
            float a = fabsf(so[n]);
            if (a > d2) { ms2 += a; c2 += 1.f; }
        }
        float a2 = ms2 / c2;
        #pragma unroll
        for (int n = 0; n < 10; n++)
            out[b * 10 + n] = tern_val(so[n], d2, a2);
    }
}

// ---------------- launch ----------------
extern "C" void kernel_launch(void* const* d_in, const int* in_sizes, int n_in,
                              void* d_out, int out_size)
{
    (void)in_sizes; (void)n_in; (void)out_size;
    const float* x       = (const float*)d_in[0];
    const float* conv1_w = (const float*)d_in[1];
    const float* conv1_b = (const float*)d_in[2];
    const float* bn1_g   = (const float*)d_in[3];
    const float* bn1_b   = (const float*)d_in[4];
    const float* conv2_w = (const float*)d_in[5];
    const float* conv2_b = (const float*)d_in[6];
    const float* bn2_g   = (const float*)d_in[7];
    const float* bn2_b   = (const float*)d_in[8];
    const float* fc1_w   = (const float*)d_in[9];
    const float* fc1_b   = (const float*)d_in[10];
    const float* fc2_w   = (const float*)d_in[11];
    const float* fc2_b   = (const float*)d_in[12];
    float* out = (float*)d_out;

    const int SMEM1 = (1584 + 32 * SC1STR) * 4;          // ~80.3 KB
    const int SMEM2 = (18432 + 8192) * 4;                // 106.5 KB -> 2 CTAs/SM
    const int SMEMF = (4096 + 8192) * 4;                 // 48 KB -> 2 CTAs/SM possible
    cudaFuncSetAttribute(k_conv1, cudaFuncAttributeMaxDynamicSharedMemorySize, SMEM1);
    cudaFuncSetAttribute(k_conv2, cudaFuncAttributeMaxDynamicSharedMemorySize, SMEM2);
    cudaFuncSetAttribute(k_fc1,   cudaFuncAttributeMaxDynamicSharedMemorySize, SMEMF);

    k_pre<<<(N_W2 + N_W1 + 255) / 256, 256>>>(conv2_w, fc1_w);
    k_conv1<<<2048, 256, SMEM1>>>(x, conv1_w, conv1_b, bn1_g, bn1_b);
    k_conv2<<<1024, 256, SMEM2>>>(conv2_b, bn2_g, bn2_b);
    k_fc1<<<dim3(4, 32, 2), 128, SMEMF>>>();
    k_head<<<2048, 128>>>(fc1_b, fc2_w, fc2_b, out);
}